// round 2
// baseline (speedup 1.0000x reference)
#include <cuda_runtime.h>
#include <math.h>
#include <stdint.h>

#define NT 2048
#define D_DIM 1024
#define M_DIM 4096
#define L_DIM 24
#define H_DIM 4
#define HD 8
#define R_DIM 64
#define NJ 32
#define LN_EPS 1e-5f
#define SCORE_SCALE 0.17677669529663687f  /* 1/(sqrt(8)*2) */

// -------- device scratch (no allocations allowed) --------
__device__ float g_WgT[M_DIM * NJ];          // (Wk * kv_ln_scale)^T : [m][j]
__device__ float g_Swg[NJ];                  // sum_m Wk[j,m]*g[m]
__device__ float g_Ck[NJ];                   // Wk @ kv_ln_bias + bk
__device__ float g_Sq[NJ];                   // sum_d Wq[j,d]*qg[d]
__device__ float g_Cq[NJ];                   // Wq @ q_ln_bias + bq
__device__ float g_OUT[(size_t)NT * H_DIM * M_DIM];  // 128 MB: out[t][h*M+m]
__device__ float g_Y[NT * R_DIM];            // Y = OUT @ outB^T

// ---------------------------------------------------------
__global__ void k_pre_wgt(const float* __restrict__ Wk, const float* __restrict__ kg) {
    int idx = blockIdx.x * 256 + threadIdx.x;   // 4096*32 = 131072
    int m = idx >> 5, j = idx & 31;
    g_WgT[idx] = Wk[j * M_DIM + m] * kg[m];
}

__global__ void k_pre_sc(const float* __restrict__ Wk, const float* __restrict__ kg,
                         const float* __restrict__ kb, const float* __restrict__ bk,
                         const float* __restrict__ Wq, const float* __restrict__ qg,
                         const float* __restrict__ qb, const float* __restrict__ bq) {
    __shared__ float red0[256];
    __shared__ float red1[256];
    int b = blockIdx.x, t = threadIdx.x;
    float s = 0.f, c = 0.f;
    if (b < 32) {
        const float* w = Wk + b * M_DIM;
        for (int m = t; m < M_DIM; m += 256) { float wv = w[m]; s += wv * kg[m]; c += wv * kb[m]; }
    } else {
        const float* w = Wq + (b - 32) * D_DIM;
        for (int d = t; d < D_DIM; d += 256) { float wv = w[d]; s += wv * qg[d]; c += wv * qb[d]; }
    }
    red0[t] = s; red1[t] = c; __syncthreads();
    for (int o = 128; o > 0; o >>= 1) {
        if (t < o) { red0[t] += red0[t + o]; red1[t] += red1[t + o]; }
        __syncthreads();
    }
    if (t == 0) {
        if (b < 32) { g_Swg[b] = red0[0]; g_Ck[b] = red1[0] + bk[b]; }
        else        { g_Sq[b - 32] = red0[0]; g_Cq[b - 32] = red1[0] + bq[b - 32]; }
    }
}

__global__ void k_zero_y() {
    int i = blockIdx.x * 256 + threadIdx.x;
    if (i < NT * R_DIM) g_Y[i] = 0.f;
}

// ---------------------------------------------------------
// Main per-token kernel: LN stats + folded K projection (pass 1), attention,
// folded V aggregation (pass 2) writing OUT scratch.
__global__ __launch_bounds__(256) void k_main(
    const float* __restrict__ base, const float* __restrict__ cfc,
    const float* __restrict__ qg, const float* __restrict__ kg,
    const float* __restrict__ kb, const float* __restrict__ Wq)
{
    __shared__ __align__(16) float s_tile[256 * 28];   // kv tile [m_local][l] stride 28
    __shared__ float s_red[8][48];
    __shared__ float s_klow[L_DIM * NJ];
    __shared__ float s_qlow[NJ];
    __shared__ float s_mu[L_DIM];
    __shared__ float s_rstd[L_DIM];
    __shared__ __align__(16) float s_w[H_DIM][L_DIM];  // attn*rstd
    __shared__ float s_scores[H_DIM][L_DIM];
    __shared__ float s_ch[H_DIM];
    __shared__ float s_xq[D_DIM];
    __shared__ float s_qstat[2];

    const int token = blockIdx.x;
    const int tid = threadIdx.x;
    const int w = tid >> 5, lane = tid & 31;
    const float* kvp = cfc + (size_t)token * (M_DIM * L_DIM);

    // ================= Q side =================
    {
        float qs = 0.f, qs2 = 0.f;
        #pragma unroll
        for (int i = 0; i < 4; i++) {
            int d = tid + i * 256;
            float v = base[(size_t)token * D_DIM + d];
            s_xq[d] = v; qs += v; qs2 += v * v;
        }
        #pragma unroll
        for (int o = 16; o > 0; o >>= 1) {
            qs  += __shfl_xor_sync(0xffffffffu, qs, o);
            qs2 += __shfl_xor_sync(0xffffffffu, qs2, o);
        }
        if (lane == 0) { s_red[w][0] = qs; s_red[w][1] = qs2; }
        // pre-scale own x entries by q_ln_scale (own-thread data only)
        #pragma unroll
        for (int i = 0; i < 4; i++) { int d = tid + i * 256; s_xq[d] *= qg[d]; }
        __syncthreads();
        if (tid == 0) {
            float S = 0.f, S2 = 0.f;
            #pragma unroll
            for (int i = 0; i < 8; i++) { S += s_red[i][0]; S2 += s_red[i][1]; }
            float mu = S * (1.f / D_DIM);
            float var = S2 * (1.f / D_DIM) - mu * mu;
            s_qstat[0] = mu; s_qstat[1] = rsqrtf(var + LN_EPS);
        }
        __syncthreads();
        float qmu = s_qstat[0], qr = s_qstat[1];
        #pragma unroll
        for (int jj = 0; jj < 4; jj++) {
            int j = w * 4 + jj;
            const float* wq = Wq + j * D_DIM;
            float p = 0.f;
            for (int d = lane; d < D_DIM; d += 32) p += wq[d] * s_xq[d];
            #pragma unroll
            for (int o = 16; o > 0; o >>= 1) p += __shfl_xor_sync(0xffffffffu, p, o);
            if (lane == 0) s_qlow[j] = qr * (p - qmu * g_Sq[j]) + g_Cq[j];
        }
    }

    // ================= K pass 1: stats + projection =================
    float ps[L_DIM], ps2[L_DIM], pacc[L_DIM];
    #pragma unroll
    for (int l = 0; l < L_DIM; l++) { ps[l] = 0.f; ps2[l] = 0.f; pacc[l] = 0.f; }

    float4 v0, v1, v2, v3, v4, v5;
    {
        const float4* src = (const float4*)(kvp + (size_t)tid * L_DIM);
        v0 = src[0]; v1 = src[1]; v2 = src[2]; v3 = src[3]; v4 = src[4]; v5 = src[5];
    }
    for (int c = 0; c < 16; c++) {
        float kv[L_DIM];
        *(float4*)&kv[0]  = v0; *(float4*)&kv[4]  = v1; *(float4*)&kv[8]  = v2;
        *(float4*)&kv[12] = v3; *(float4*)&kv[16] = v4; *(float4*)&kv[20] = v5;
        #pragma unroll
        for (int l = 0; l < L_DIM; l++) { ps[l] += kv[l]; ps2[l] += kv[l] * kv[l]; }
        float4* dst = (float4*)(s_tile + tid * 28);
        dst[0] = v0; dst[1] = v1; dst[2] = v2; dst[3] = v3; dst[4] = v4; dst[5] = v5;
        __syncthreads();
        if (c < 15) {  // prefetch next chunk, overlapped with proj FFMAs
            const float4* src = (const float4*)(kvp + (size_t)((c + 1) * 256 + tid) * L_DIM);
            v0 = src[0]; v1 = src[1]; v2 = src[2]; v3 = src[3]; v4 = src[4]; v5 = src[5];
        }
        const float* wrow = g_WgT + ((c * 256 + w * 32) * NJ) + lane;
        #pragma unroll 4
        for (int mm = 0; mm < 32; mm++) {
            float wv = wrow[mm * NJ];
            const float4* kk4 = (const float4*)(s_tile + (w * 32 + mm) * 28);
            float kk[L_DIM];
            *(float4*)&kk[0]  = kk4[0]; *(float4*)&kk[4]  = kk4[1]; *(float4*)&kk[8]  = kk4[2];
            *(float4*)&kk[12] = kk4[3]; *(float4*)&kk[16] = kk4[4]; *(float4*)&kk[20] = kk4[5];
            #pragma unroll
            for (int l = 0; l < L_DIM; l++) pacc[l] += kk[l] * wv;
        }
        __syncthreads();
    }

    // stats reduce across block
    #pragma unroll
    for (int l = 0; l < L_DIM; l++) {
        float a = ps[l], b = ps2[l];
        #pragma unroll
        for (int o = 16; o > 0; o >>= 1) {
            a += __shfl_xor_sync(0xffffffffu, a, o);
            b += __shfl_xor_sync(0xffffffffu, b, o);
        }
        if (lane == 0) { s_red[w][l] = a; s_red[w][24 + l] = b; }
    }
    __syncthreads();
    if (tid < L_DIM) {
        float S = 0.f, S2 = 0.f;
        #pragma unroll
        for (int i = 0; i < 8; i++) { S += s_red[i][tid]; S2 += s_red[i][24 + tid]; }
        float mu = S * (1.f / M_DIM);
        float var = S2 * (1.f / M_DIM) - mu * mu;
        s_mu[tid] = mu; s_rstd[tid] = rsqrtf(var + LN_EPS);
    }
    // proj reduce across warps (reuse tile smem)
    float* pr = s_tile;   // [w][l*32+j]
    #pragma unroll
    for (int l = 0; l < L_DIM; l++) pr[w * 768 + l * 32 + lane] = pacc[l];
    __syncthreads();
    for (int e = tid; e < 768; e += 256) {
        float P = 0.f;
        #pragma unroll
        for (int i = 0; i < 8; i++) P += pr[i * 768 + e];
        int l = e >> 5, j = e & 31;
        s_klow[e] = s_rstd[l] * (P - s_mu[l] * g_Swg[j]) + g_Ck[j];
    }
    __syncthreads();

    // ================= scores + softmax =================
    if (tid < H_DIM * L_DIM) {
        int h = tid / L_DIM, l = tid - h * L_DIM;
        float s = 0.f;
        #pragma unroll
        for (int d = 0; d < HD; d++) s += s_qlow[h * HD + d] * s_klow[l * NJ + h * HD + d];
        s *= SCORE_SCALE;
        if (isnan(s)) s = -INFINITY;
        s_scores[h][l] = s;
    }
    __syncthreads();
    if (tid < H_DIM) {
        int h = tid;
        float mx = -INFINITY;
        #pragma unroll
        for (int l = 0; l < L_DIM; l++) mx = fmaxf(mx, s_scores[h][l]);
        float e[L_DIM]; float sum = 0.f;
        #pragma unroll
        for (int l = 0; l < L_DIM; l++) { e[l] = expf(s_scores[h][l] - mx); sum += e[l]; }
        float inv = 1.f / sum;
        float ch = 0.f;
        #pragma unroll
        for (int l = 0; l < L_DIM; l++) {
            float wv = e[l] * inv * s_rstd[l];
            s_w[h][l] = wv;
            ch += wv * s_mu[l];
        }
        s_ch[h] = ch;
    }
    __syncthreads();

    // ================= K pass 2: out[h][m] =================
    const float ch0 = s_ch[0], ch1 = s_ch[1], ch2 = s_ch[2], ch3 = s_ch[3];
    float* outp = g_OUT + (size_t)token * (H_DIM * M_DIM);
    for (int c = 0; c < 16; c++) {
        int m = c * 256 + tid;
        const float4* src = (const float4*)(kvp + (size_t)m * L_DIM);
        float kv[L_DIM];
        *(float4*)&kv[0]  = src[0]; *(float4*)&kv[4]  = src[1]; *(float4*)&kv[8]  = src[2];
        *(float4*)&kv[12] = src[3]; *(float4*)&kv[16] = src[4]; *(float4*)&kv[20] = src[5];
        float A0 = 0.f, A1 = 0.f, A2 = 0.f, A3 = 0.f;
        #pragma unroll
        for (int l4 = 0; l4 < 6; l4++) {
            float4 w0 = *(const float4*)&s_w[0][l4 * 4];
            float4 w1 = *(const float4*)&s_w[1][l4 * 4];
            float4 w2 = *(const float4*)&s_w[2][l4 * 4];
            float4 w3 = *(const float4*)&s_w[3][l4 * 4];
            float k0 = kv[l4 * 4], k1 = kv[l4 * 4 + 1], k2 = kv[l4 * 4 + 2], k3 = kv[l4 * 4 + 3];
            A0 += w0.x * k0 + w0.y * k1 + w0.z * k2 + w0.w * k3;
            A1 += w1.x * k0 + w1.y * k1 + w1.z * k2 + w1.w * k3;
            A2 += w2.x * k0 + w2.y * k1 + w2.z * k2 + w2.w * k3;
            A3 += w3.x * k0 + w3.y * k1 + w3.z * k2 + w3.w * k3;
        }
        float gm = kg[m], bm = kb[m];
        outp[0 * M_DIM + m] = gm * (A0 - ch0) + bm;
        outp[1 * M_DIM + m] = gm * (A1 - ch1) + bm;
        outp[2 * M_DIM + m] = gm * (A2 - ch2) + bm;
        outp[3 * M_DIM + m] = gm * (A3 - ch3) + bm;
    }
}

// ---------------------------------------------------------
// Y = OUT (2048 x 16384) @ outB^T (16384 x 64), split-K with atomics.
__global__ __launch_bounds__(128) void k_y(const float* __restrict__ outB) {
    __shared__ __align__(16) float sB[64 * 66];
    __shared__ __align__(16) float sO[64 * 20];
    const int bt = blockIdx.x & 127;      // token tile (16 tokens)
    const int ks = blockIdx.x >> 7;       // K split (0..3)
    const int tid = threadIdx.x;
    const int r2 = (tid & 31) * 2;
    const int tg = tid >> 5;              // token group (4 tokens)
    float acc[8] = {0.f, 0.f, 0.f, 0.f, 0.f, 0.f, 0.f, 0.f};
    const int k0base = ks * 4096;
    const float* outp = g_OUT + (size_t)bt * 16 * 16384;

    for (int kt = 0; kt < 64; kt++) {
        int k0 = k0base + kt * 64;
        for (int i = tid; i < 4096; i += 128) {
            int r = i >> 6, kk = i & 63;
            sB[kk * 66 + r] = outB[(size_t)r * 16384 + k0 + kk];
        }
        for (int i = tid; i < 1024; i += 128) {
            int t = i >> 6, kk = i & 63;
            sO[kk * 20 + t] = outp[(size_t)t * 16384 + k0 + kk];
        }
        __syncthreads();
        #pragma unroll 8
        for (int kk = 0; kk < 64; kk++) {
            float2 b2 = *(const float2*)&sB[kk * 66 + r2];
            float4 o4 = *(const float4*)&sO[kk * 20 + tg * 4];
            acc[0] += o4.x * b2.x; acc[1] += o4.x * b2.y;
            acc[2] += o4.y * b2.x; acc[3] += o4.y * b2.y;
            acc[4] += o4.z * b2.x; acc[5] += o4.z * b2.y;
            acc[6] += o4.w * b2.x; acc[7] += o4.w * b2.y;
        }
        __syncthreads();
    }
    int tbase = bt * 16 + tg * 4;
    #pragma unroll
    for (int i = 0; i < 4; i++) {
        atomicAdd(&g_Y[(tbase + i) * R_DIM + r2],     acc[i * 2]);
        atomicAdd(&g_Y[(tbase + i) * R_DIM + r2 + 1], acc[i * 2 + 1]);
    }
}

// ---------------------------------------------------------
// result = base + scale * (Y @ outA^T + out_bias)
__global__ __launch_bounds__(256) void k_final(
    const float* __restrict__ base, const float* __restrict__ outA,
    const float* __restrict__ out_bias, const float* __restrict__ scale_p,
    float* __restrict__ out)
{
    __shared__ __align__(16) float yc[8][64];
    const int t0 = blockIdx.x * 8;
    const int tid = threadIdx.x;
    for (int e = tid; e < 512; e += 256) yc[e >> 6][e & 63] = g_Y[t0 * R_DIM + e];
    __syncthreads();
    const float scale = *scale_p;
    for (int d = tid; d < D_DIM; d += 256) {
        const float4* ar = (const float4*)(outA + d * R_DIM);
        float acc[8] = {0.f, 0.f, 0.f, 0.f, 0.f, 0.f, 0.f, 0.f};
        #pragma unroll
        for (int rr = 0; rr < 16; rr++) {
            float4 a = ar[rr];
            #pragma unroll
            for (int tt = 0; tt < 8; tt++) {
                float4 y4 = *(const float4*)&yc[tt][rr * 4];
                acc[tt] += a.x * y4.x + a.y * y4.y + a.z * y4.z + a.w * y4.w;
            }
        }
        float bias = out_bias[d];
        #pragma unroll
        for (int tt = 0; tt < 8; tt++) {
            int t = t0 + tt;
            out[(size_t)t * D_DIM + d] = base[(size_t)t * D_DIM + d] + scale * (acc[tt] + bias);
        }
    }
}

// ---------------------------------------------------------
extern "C" void kernel_launch(void* const* d_in, const int* in_sizes, int n_in,
                              void* d_out, int out_size) {
    const float* base  = (const float*)d_in[0];
    const float* cfc   = (const float*)d_in[1];
    const float* qg    = (const float*)d_in[2];
    const float* qb    = (const float*)d_in[3];
    const float* kg    = (const float*)d_in[4];
    const float* kb    = (const float*)d_in[5];
    const float* Wq    = (const float*)d_in[6];
    const float* bq    = (const float*)d_in[7];
    const float* Wk    = (const float*)d_in[8];
    const float* bk    = (const float*)d_in[9];
    const float* outA  = (const float*)d_in[10];
    const float* outB  = (const float*)d_in[11];
    const float* obias = (const float*)d_in[12];
    const float* ascale= (const float*)d_in[13];
    float* out = (float*)d_out;

    k_pre_wgt<<<512, 256>>>(Wk, kg);
    k_pre_sc<<<64, 256>>>(Wk, kg, kb, bk, Wq, qg, qb, bq);
    k_zero_y<<<512, 256>>>();
    k_main<<<NT, 256>>>(base, cfc, qg, kg, kb, Wq);
    k_y<<<512, 128>>>(outB);
    k_final<<<NT / 8, 256>>>(base, outA, obias, ascale, out);
}

// round 4
// speedup vs baseline: 1.1825x; 1.1825x over previous
#include <cuda_runtime.h>
#include <math.h>
#include <stdint.h>

#define NT 2048
#define D_DIM 1024
#define M_DIM 4096
#define L_DIM 24
#define H_DIM 4
#define HD 8
#define R_DIM 64
#define NJ 32
#define LN_EPS 1e-5f
#define SCORE_SCALE 0.17677669529663687f  /* 1/(sqrt(8)*2) */

typedef unsigned long long ull;

// ---- f32x2 packed helpers (sm_100+) ----
__device__ __forceinline__ void fma2(ull& d, ull a, ull b) {
    asm("fma.rn.f32x2 %0,%1,%2,%3;" : "=l"(d) : "l"(a), "l"(b), "l"(d));
}
__device__ __forceinline__ void add2(ull& d, ull a) {
    asm("add.rn.f32x2 %0,%1,%2;" : "=l"(d) : "l"(d), "l"(a));
}
__device__ __forceinline__ ull pack2(float lo, float hi) {
    ull r; asm("mov.b64 %0,{%1,%2};" : "=l"(r) : "f"(lo), "f"(hi)); return r;
}
__device__ __forceinline__ void unpack2(ull v, float& lo, float& hi) {
    asm("mov.b64 {%0,%1},%2;" : "=f"(lo), "=f"(hi) : "l"(v));
}

union F4U { float4 f; ull u[2]; };

// -------- device scratch (no allocations allowed) --------
__device__ float g_WgT[M_DIM * NJ];          // (Wk * kv_ln_scale)^T : [m][j]
__device__ float g_Swg[NJ];                  // sum_m Wk[j,m]*g[m]
__device__ float g_Ck[NJ];                   // Wk @ kv_ln_bias + bk
__device__ float g_Sq[NJ];                   // sum_d Wq[j,d]*qg[d]
__device__ float g_Cq[NJ];                   // Wq @ q_ln_bias + bq
__device__ float g_OUT[(size_t)NT * H_DIM * M_DIM];  // 128 MB: out[t][h*M+m]
__device__ float g_Y[NT * R_DIM];            // Y = OUT @ outB^T

// ---------------------------------------------------------
__global__ void k_pre_wgt(const float* __restrict__ Wk, const float* __restrict__ kg) {
    int idx = blockIdx.x * 256 + threadIdx.x;   // 4096*32 = 131072
    int m = idx >> 5, j = idx & 31;
    g_WgT[idx] = Wk[j * M_DIM + m] * kg[m];
}

__global__ void k_pre_sc(const float* __restrict__ Wk, const float* __restrict__ kg,
                         const float* __restrict__ kb, const float* __restrict__ bk,
                         const float* __restrict__ Wq, const float* __restrict__ qg,
                         const float* __restrict__ qb, const float* __restrict__ bq) {
    __shared__ float red0[256];
    __shared__ float red1[256];
    int b = blockIdx.x, t = threadIdx.x;
    float s = 0.f, c = 0.f;
    if (b < 32) {
        const float* w = Wk + b * M_DIM;
        for (int m = t; m < M_DIM; m += 256) { float wv = w[m]; s += wv * kg[m]; c += wv * kb[m]; }
    } else {
        const float* w = Wq + (b - 32) * D_DIM;
        for (int d = t; d < D_DIM; d += 256) { float wv = w[d]; s += wv * qg[d]; c += wv * qb[d]; }
    }
    red0[t] = s; red1[t] = c; __syncthreads();
    for (int o = 128; o > 0; o >>= 1) {
        if (t < o) { red0[t] += red0[t + o]; red1[t] += red1[t + o]; }
        __syncthreads();
    }
    if (t == 0) {
        if (b < 32) { g_Swg[b] = red0[0]; g_Ck[b] = red1[0] + bk[b]; }
        else        { g_Sq[b - 32] = red0[0]; g_Cq[b - 32] = red1[0] + bq[b - 32]; }
    }
}

__global__ void k_zero_y() {
    int i = blockIdx.x * 256 + threadIdx.x;
    if (i < NT * R_DIM) g_Y[i] = 0.f;
}

// ---------------------------------------------------------
// Main per-token kernel: LN stats + folded K projection (pass 1), attention,
// folded V aggregation (pass 2) writing OUT scratch. f32x2 packed math.
__global__ __launch_bounds__(256) void k_main(
    const float* __restrict__ base, const float* __restrict__ cfc,
    const float* __restrict__ qg, const float* __restrict__ kg,
    const float* __restrict__ kb, const float* __restrict__ Wq)
{
    __shared__ __align__(16) float s_tile[256 * 28];   // kv tile [m_local][l] stride 28
    __shared__ float s_red[8][48];
    __shared__ float s_klow[L_DIM * NJ];
    __shared__ float s_qlow[NJ];
    __shared__ float s_mu[L_DIM];
    __shared__ float s_rstd[L_DIM];
    __shared__ __align__(16) float s_w[H_DIM][L_DIM];  // attn*rstd
    __shared__ float s_scores[H_DIM][L_DIM];
    __shared__ float s_ch[H_DIM];
    __shared__ float s_xq[D_DIM];
    __shared__ float s_qstat[2];

    const int token = blockIdx.x;
    const int tid = threadIdx.x;
    const int w = tid >> 5, lane = tid & 31;
    const float* kvp = cfc + (size_t)token * (M_DIM * L_DIM);

    // ================= Q side =================
    {
        float qs = 0.f, qs2 = 0.f;
        #pragma unroll
        for (int i = 0; i < 4; i++) {
            int d = tid + i * 256;
            float v = base[(size_t)token * D_DIM + d];
            s_xq[d] = v; qs += v; qs2 += v * v;
        }
        #pragma unroll
        for (int o = 16; o > 0; o >>= 1) {
            qs  += __shfl_xor_sync(0xffffffffu, qs, o);
            qs2 += __shfl_xor_sync(0xffffffffu, qs2, o);
        }
        if (lane == 0) { s_red[w][0] = qs; s_red[w][1] = qs2; }
        #pragma unroll
        for (int i = 0; i < 4; i++) { int d = tid + i * 256; s_xq[d] *= qg[d]; }
        __syncthreads();
        if (tid == 0) {
            float S = 0.f, S2 = 0.f;
            #pragma unroll
            for (int i = 0; i < 8; i++) { S += s_red[i][0]; S2 += s_red[i][1]; }
            float mu = S * (1.f / D_DIM);
            float var = S2 * (1.f / D_DIM) - mu * mu;
            s_qstat[0] = mu; s_qstat[1] = rsqrtf(var + LN_EPS);
        }
        __syncthreads();
        float qmu = s_qstat[0], qr = s_qstat[1];
        #pragma unroll
        for (int jj = 0; jj < 4; jj++) {
            int j = w * 4 + jj;
            const float* wq = Wq + j * D_DIM;
            float p = 0.f;
            for (int d = lane; d < D_DIM; d += 32) p += wq[d] * s_xq[d];
            #pragma unroll
            for (int o = 16; o > 0; o >>= 1) p += __shfl_xor_sync(0xffffffffu, p, o);
            if (lane == 0) s_qlow[j] = qr * (p - qmu * g_Sq[j]) + g_Cq[j];
        }
    }

    // ================= K pass 1: stats + projection (f32x2) =================
    ull pS[12], pQ[12], pA[12];
    #pragma unroll
    for (int i = 0; i < 12; i++) { pS[i] = 0ull; pQ[i] = 0ull; pA[i] = 0ull; }

    float4 v0, v1, v2, v3, v4, v5;
    {
        const float4* src = (const float4*)(kvp + (size_t)tid * L_DIM);
        v0 = src[0]; v1 = src[1]; v2 = src[2]; v3 = src[3]; v4 = src[4]; v5 = src[5];
    }
    for (int c = 0; c < 16; c++) {
        // stats from registers + store tile
        {
            F4U U;
            float4* dst = (float4*)(s_tile + tid * 28);
            U.f = v0; dst[0] = v0; add2(pS[0],  U.u[0]); fma2(pQ[0],  U.u[0], U.u[0]);
                                   add2(pS[1],  U.u[1]); fma2(pQ[1],  U.u[1], U.u[1]);
            U.f = v1; dst[1] = v1; add2(pS[2],  U.u[0]); fma2(pQ[2],  U.u[0], U.u[0]);
                                   add2(pS[3],  U.u[1]); fma2(pQ[3],  U.u[1], U.u[1]);
            U.f = v2; dst[2] = v2; add2(pS[4],  U.u[0]); fma2(pQ[4],  U.u[0], U.u[0]);
                                   add2(pS[5],  U.u[1]); fma2(pQ[5],  U.u[1], U.u[1]);
            U.f = v3; dst[3] = v3; add2(pS[6],  U.u[0]); fma2(pQ[6],  U.u[0], U.u[0]);
                                   add2(pS[7],  U.u[1]); fma2(pQ[7],  U.u[1], U.u[1]);
            U.f = v4; dst[4] = v4; add2(pS[8],  U.u[0]); fma2(pQ[8],  U.u[0], U.u[0]);
                                   add2(pS[9],  U.u[1]); fma2(pQ[9],  U.u[1], U.u[1]);
            U.f = v5; dst[5] = v5; add2(pS[10], U.u[0]); fma2(pQ[10], U.u[0], U.u[0]);
                                   add2(pS[11], U.u[1]); fma2(pQ[11], U.u[1], U.u[1]);
        }
        __syncthreads();
        if (c < 15) {  // prefetch next chunk, overlapped with proj FFMAs
            const float4* src = (const float4*)(kvp + (size_t)((c + 1) * 256 + tid) * L_DIM);
            v0 = src[0]; v1 = src[1]; v2 = src[2]; v3 = src[3]; v4 = src[4]; v5 = src[5];
        }
        const float* wrow = g_WgT + ((c * 256 + w * 32) * NJ) + lane;
        #pragma unroll 4
        for (int mm = 0; mm < 32; mm++) {
            float wv = wrow[mm * NJ];
            ull w2 = pack2(wv, wv);
            const float4* kk4 = (const float4*)(s_tile + (w * 32 + mm) * 28);
            F4U K0, K1, K2, K3, K4, K5;
            K0.f = kk4[0]; K1.f = kk4[1]; K2.f = kk4[2];
            K3.f = kk4[3]; K4.f = kk4[4]; K5.f = kk4[5];
            fma2(pA[0],  K0.u[0], w2); fma2(pA[1],  K0.u[1], w2);
            fma2(pA[2],  K1.u[0], w2); fma2(pA[3],  K1.u[1], w2);
            fma2(pA[4],  K2.u[0], w2); fma2(pA[5],  K2.u[1], w2);
            fma2(pA[6],  K3.u[0], w2); fma2(pA[7],  K3.u[1], w2);
            fma2(pA[8],  K4.u[0], w2); fma2(pA[9],  K4.u[1], w2);
            fma2(pA[10], K5.u[0], w2); fma2(pA[11], K5.u[1], w2);
        }
        __syncthreads();
    }

    // unpack packed accumulators
    float ps[L_DIM], ps2[L_DIM], pacc[L_DIM];
    #pragma unroll
    for (int i = 0; i < 12; i++) {
        unpack2(pS[i], ps[2 * i],  ps[2 * i + 1]);
        unpack2(pQ[i], ps2[2 * i], ps2[2 * i + 1]);
        unpack2(pA[i], pacc[2 * i], pacc[2 * i + 1]);
    }

    // stats reduce across block
    #pragma unroll
    for (int l = 0; l < L_DIM; l++) {
        float a = ps[l], b = ps2[l];
        #pragma unroll
        for (int o = 16; o > 0; o >>= 1) {
            a += __shfl_xor_sync(0xffffffffu, a, o);
            b += __shfl_xor_sync(0xffffffffu, b, o);
        }
        if (lane == 0) { s_red[w][l] = a; s_red[w][24 + l] = b; }
    }
    __syncthreads();
    if (tid < L_DIM) {
        float S = 0.f, S2 = 0.f;
        #pragma unroll
        for (int i = 0; i < 8; i++) { S += s_red[i][tid]; S2 += s_red[i][24 + tid]; }
        float mu = S * (1.f / M_DIM);
        float var = S2 * (1.f / M_DIM) - mu * mu;
        s_mu[tid] = mu; s_rstd[tid] = rsqrtf(var + LN_EPS);
    }
    // proj reduce across warps (reuse tile smem)
    float* pr = s_tile;   // [w][l*32+j]
    #pragma unroll
    for (int l = 0; l < L_DIM; l++) pr[w * 768 + l * 32 + lane] = pacc[l];
    __syncthreads();
    for (int e = tid; e < 768; e += 256) {
        float P = 0.f;
        #pragma unroll
        for (int i = 0; i < 8; i++) P += pr[i * 768 + e];
        int l = e >> 5, j = e & 31;
        s_klow[e] = s_rstd[l] * (P - s_mu[l] * g_Swg[j]) + g_Ck[j];
    }
    __syncthreads();

    // ================= scores + softmax =================
    if (tid < H_DIM * L_DIM) {
        int h = tid / L_DIM, l = tid - h * L_DIM;
        float s = 0.f;
        #pragma unroll
        for (int d = 0; d < HD; d++) s += s_qlow[h * HD + d] * s_klow[l * NJ + h * HD + d];
        s *= SCORE_SCALE;
        if (isnan(s)) s = -INFINITY;
        s_scores[h][l] = s;
    }
    __syncthreads();
    if (tid < H_DIM) {
        int h = tid;
        float mx = -INFINITY;
        #pragma unroll
        for (int l = 0; l < L_DIM; l++) mx = fmaxf(mx, s_scores[h][l]);
        float e[L_DIM]; float sum = 0.f;
        #pragma unroll
        for (int l = 0; l < L_DIM; l++) { e[l] = expf(s_scores[h][l] - mx); sum += e[l]; }
        float inv = 1.f / sum;
        float ch = 0.f;
        #pragma unroll
        for (int l = 0; l < L_DIM; l++) {
            float wv = e[l] * inv * s_rstd[l];
            s_w[h][l] = wv;
            ch += wv * s_mu[l];
        }
        s_ch[h] = ch;
    }
    __syncthreads();

    // ================= K pass 2: out[h][m] (f32x2) =================
    const float ch0 = s_ch[0], ch1 = s_ch[1], ch2 = s_ch[2], ch3 = s_ch[3];
    float* outp = g_OUT + (size_t)token * (H_DIM * M_DIM);
    for (int c = 0; c < 16; c++) {
        int m = c * 256 + tid;
        const float4* src = (const float4*)(kvp + (size_t)m * L_DIM);
        F4U kvu[6];
        #pragma unroll
        for (int i = 0; i < 6; i++) kvu[i].f = src[i];
        ull a0 = 0ull, a1 = 0ull, a2 = 0ull, a3 = 0ull;
        #pragma unroll
        for (int l4 = 0; l4 < 6; l4++) {
            F4U W0, W1, W2, W3;
            W0.f = *(const float4*)&s_w[0][l4 * 4];
            W1.f = *(const float4*)&s_w[1][l4 * 4];
            W2.f = *(const float4*)&s_w[2][l4 * 4];
            W3.f = *(const float4*)&s_w[3][l4 * 4];
            fma2(a0, kvu[l4].u[0], W0.u[0]); fma2(a0, kvu[l4].u[1], W0.u[1]);
            fma2(a1, kvu[l4].u[0], W1.u[0]); fma2(a1, kvu[l4].u[1], W1.u[1]);
            fma2(a2, kvu[l4].u[0], W2.u[0]); fma2(a2, kvu[l4].u[1], W2.u[1]);
            fma2(a3, kvu[l4].u[0], W3.u[0]); fma2(a3, kvu[l4].u[1], W3.u[1]);
        }
        float x, y, A0, A1, A2, A3;
        unpack2(a0, x, y); A0 = x + y;
        unpack2(a1, x, y); A1 = x + y;
        unpack2(a2, x, y); A2 = x + y;
        unpack2(a3, x, y); A3 = x + y;
        float gm = kg[m], bm = kb[m];
        outp[0 * M_DIM + m] = gm * (A0 - ch0) + bm;
        outp[1 * M_DIM + m] = gm * (A1 - ch1) + bm;
        outp[2 * M_DIM + m] = gm * (A2 - ch2) + bm;
        outp[3 * M_DIM + m] = gm * (A3 - ch3) + bm;
    }
}

// ---------------------------------------------------------
// Y = OUT (2048 x 16384) @ outB^T (16384 x 64), split-K(8) with atomics, f32x2.
__global__ __launch_bounds__(128) void k_y(const float* __restrict__ outB) {
    __shared__ __align__(16) float sB[64 * 66];
    __shared__ __align__(16) float sO[64 * 20];
    const int bt = blockIdx.x & 127;      // token tile (16 tokens)
    const int ks = blockIdx.x >> 7;       // K split (0..7)
    const int tid = threadIdx.x;
    const int r2 = (tid & 31) * 2;
    const int tg = tid >> 5;              // token group (4 tokens)
    ull acc00 = 0ull, acc01 = 0ull, acc10 = 0ull, acc11 = 0ull;
    const int k0base = ks * 2048;
    const float* outp = g_OUT + (size_t)bt * 16 * 16384;

    for (int kt = 0; kt < 32; kt++) {
        int k0 = k0base + kt * 64;
        for (int i = tid; i < 4096; i += 128) {
            int r = i >> 6, kk = i & 63;
            sB[kk * 66 + r] = outB[(size_t)r * 16384 + k0 + kk];
        }
        for (int i = tid; i < 1024; i += 128) {
            int t = i >> 6, kk = i & 63;
            sO[kk * 20 + t] = outp[(size_t)t * 16384 + k0 + kk];
        }
        __syncthreads();
        #pragma unroll 8
        for (int kk = 0; kk < 64; kk++) {
            float2 b2 = *(const float2*)&sB[kk * 66 + r2];
            ull bx = pack2(b2.x, b2.x);
            ull by = pack2(b2.y, b2.y);
            F4U O; O.f = *(const float4*)&sO[kk * 20 + tg * 4];
            fma2(acc00, O.u[0], bx); fma2(acc10, O.u[0], by);
            fma2(acc01, O.u[1], bx); fma2(acc11, O.u[1], by);
        }
        __syncthreads();
    }
    int tbase = bt * 16 + tg * 4;
    float t0, t1, t2, t3;
    unpack2(acc00, t0, t1); unpack2(acc01, t2, t3);
    atomicAdd(&g_Y[(tbase + 0) * R_DIM + r2], t0);
    atomicAdd(&g_Y[(tbase + 1) * R_DIM + r2], t1);
    atomicAdd(&g_Y[(tbase + 2) * R_DIM + r2], t2);
    atomicAdd(&g_Y[(tbase + 3) * R_DIM + r2], t3);
    unpack2(acc10, t0, t1); unpack2(acc11, t2, t3);
    atomicAdd(&g_Y[(tbase + 0) * R_DIM + r2 + 1], t0);
    atomicAdd(&g_Y[(tbase + 1) * R_DIM + r2 + 1], t1);
    atomicAdd(&g_Y[(tbase + 2) * R_DIM + r2 + 1], t2);
    atomicAdd(&g_Y[(tbase + 3) * R_DIM + r2 + 1], t3);
}

// ---------------------------------------------------------
// result = base + scale * (Y @ outA^T + out_bias)
__global__ __launch_bounds__(256) void k_final(
    const float* __restrict__ base, const float* __restrict__ outA,
    const float* __restrict__ out_bias, const float* __restrict__ scale_p,
    float* __restrict__ out)
{
    __shared__ __align__(16) float yc[8][64];
    const int t0 = blockIdx.x * 8;
    const int tid = threadIdx.x;
    for (int e = tid; e < 512; e += 256) yc[e >> 6][e & 63] = g_Y[t0 * R_DIM + e];
    __syncthreads();
    const float scale = *scale_p;
    for (int d = tid; d < D_DIM; d += 256) {
        const float4* ar = (const float4*)(outA + d * R_DIM);
        float acc[8] = {0.f, 0.f, 0.f, 0.f, 0.f, 0.f, 0.f, 0.f};
        #pragma unroll
        for (int rr = 0; rr < 16; rr++) {
            float4 a = ar[rr];
            #pragma unroll
            for (int tt = 0; tt < 8; tt++) {
                float4 y4 = *(const float4*)&yc[tt][rr * 4];
                acc[tt] += a.x * y4.x + a.y * y4.y + a.z * y4.z + a.w * y4.w;
            }
        }
        float bias = out_bias[d];
        #pragma unroll
        for (int tt = 0; tt < 8; tt++) {
            int t = t0 + tt;
            out[(size_t)t * D_DIM + d] = base[(size_t)t * D_DIM + d] + scale * (acc[tt] + bias);
        }
    }
}

// ---------------------------------------------------------
extern "C" void kernel_launch(void* const* d_in, const int* in_sizes, int n_in,
                              void* d_out, int out_size) {
    const float* base  = (const float*)d_in[0];
    const float* cfc   = (const float*)d_in[1];
    const float* qg    = (const float*)d_in[2];
    const float* qb    = (const float*)d_in[3];
    const float* kg    = (const float*)d_in[4];
    const float* kb    = (const float*)d_in[5];
    const float* Wq    = (const float*)d_in[6];
    const float* bq    = (const float*)d_in[7];
    const float* Wk    = (const float*)d_in[8];
    const float* bk    = (const float*)d_in[9];
    const float* outA  = (const float*)d_in[10];
    const float* outB  = (const float*)d_in[11];
    const float* obias = (const float*)d_in[12];
    const float* ascale= (const float*)d_in[13];
    float* out = (float*)d_out;

    k_pre_wgt<<<512, 256>>>(Wk, kg);
    k_pre_sc<<<64, 256>>>(Wk, kg, kb, bk, Wq, qg, qb, bq);
    k_zero_y<<<512, 256>>>();
    k_main<<<NT, 256>>>(base, cfc, qg, kg, kb, Wq);
    k_y<<<1024, 128>>>(outB);
    k_final<<<NT / 8, 256>>>(base, outA, obias, ascale, out);
}

// round 5
// speedup vs baseline: 1.1862x; 1.0032x over previous
#include <cuda_runtime.h>
#include <math.h>
#include <stdint.h>

#define NT 2048
#define D_DIM 1024
#define M_DIM 4096
#define L_DIM 24
#define H_DIM 4
#define HD 8
#define R_DIM 64
#define NJ 32
#define LN_EPS 1e-5f
#define SCORE_SCALE 0.17677669529663687f  /* 1/(sqrt(8)*2) */

typedef unsigned long long ull;

// ---- f32x2 packed helpers (sm_100+) ----
__device__ __forceinline__ void fma2(ull& d, ull a, ull b) {
    asm("fma.rn.f32x2 %0,%1,%2,%3;" : "=l"(d) : "l"(a), "l"(b), "l"(d));
}
__device__ __forceinline__ void add2(ull& d, ull a) {
    asm("add.rn.f32x2 %0,%1,%2;" : "=l"(d) : "l"(d), "l"(a));
}
__device__ __forceinline__ ull pack2(float lo, float hi) {
    ull r; asm("mov.b64 %0,{%1,%2};" : "=l"(r) : "f"(lo), "f"(hi)); return r;
}
__device__ __forceinline__ void unpack2(ull v, float& lo, float& hi) {
    asm("mov.b64 {%0,%1},%2;" : "=f"(lo), "=f"(hi) : "l"(v));
}

union F4U { float4 f; ull u[2]; };

// -------- device scratch (no allocations allowed) --------
__device__ float g_WgT[M_DIM * NJ];          // (Wk * kv_ln_scale)^T : [m][j]
__device__ float g_Swg[NJ];                  // sum_m Wk[j,m]*g[m]
__device__ float g_Ck[NJ];                   // Wk @ kv_ln_bias + bk
__device__ float g_Sq[NJ];                   // sum_d Wq[j,d]*qg[d]
__device__ float g_Cq[NJ];                   // Wq @ q_ln_bias + bq
__device__ float g_OUT[(size_t)NT * H_DIM * M_DIM];  // 128 MB: out[t][h*M+m]
__device__ float g_Y[NT * R_DIM];            // Y = OUT @ outB^T

// ---------------------------------------------------------
__global__ void k_pre_wgt(const float* __restrict__ Wk, const float* __restrict__ kg) {
    int idx = blockIdx.x * 256 + threadIdx.x;   // 4096*32 = 131072
    int m = idx >> 5, j = idx & 31;
    g_WgT[idx] = Wk[j * M_DIM + m] * kg[m];
}

__global__ void k_pre_sc(const float* __restrict__ Wk, const float* __restrict__ kg,
                         const float* __restrict__ kb, const float* __restrict__ bk,
                         const float* __restrict__ Wq, const float* __restrict__ qg,
                         const float* __restrict__ qb, const float* __restrict__ bq) {
    __shared__ float red0[256];
    __shared__ float red1[256];
    int b = blockIdx.x, t = threadIdx.x;
    float s = 0.f, c = 0.f;
    if (b < 32) {
        const float* w = Wk + b * M_DIM;
        for (int m = t; m < M_DIM; m += 256) { float wv = w[m]; s += wv * kg[m]; c += wv * kb[m]; }
    } else {
        const float* w = Wq + (b - 32) * D_DIM;
        for (int d = t; d < D_DIM; d += 256) { float wv = w[d]; s += wv * qg[d]; c += wv * qb[d]; }
    }
    red0[t] = s; red1[t] = c; __syncthreads();
    for (int o = 128; o > 0; o >>= 1) {
        if (t < o) { red0[t] += red0[t + o]; red1[t] += red1[t + o]; }
        __syncthreads();
    }
    if (t == 0) {
        if (b < 32) { g_Swg[b] = red0[0]; g_Ck[b] = red1[0] + bk[b]; }
        else        { g_Sq[b - 32] = red0[0]; g_Cq[b - 32] = red1[0] + bq[b - 32]; }
    }
}

__global__ void k_zero_y() {
    int i = blockIdx.x * 256 + threadIdx.x;
    if (i < NT * R_DIM) g_Y[i] = 0.f;
}

// ---------------------------------------------------------
// Main per-token kernel: LN stats + folded K projection (pass 1), attention,
// folded V aggregation (pass 2) writing OUT scratch. f32x2 packed math.
__global__ __launch_bounds__(256) void k_main(
    const float* __restrict__ base, const float* __restrict__ cfc,
    const float* __restrict__ qg, const float* __restrict__ kg,
    const float* __restrict__ kb, const float* __restrict__ Wq)
{
    __shared__ __align__(16) float s_tile[256 * 28];   // kv tile [m_local][l] stride 28
    __shared__ float s_red[8][48];
    __shared__ float s_klow[L_DIM * NJ];
    __shared__ float s_qlow[NJ];
    __shared__ float s_mu[L_DIM];
    __shared__ float s_rstd[L_DIM];
    __shared__ __align__(16) float s_w[H_DIM][L_DIM];  // attn*rstd
    __shared__ float s_scores[H_DIM][L_DIM];
    __shared__ float s_ch[H_DIM];
    __shared__ float s_xq[D_DIM];
    __shared__ float s_qstat[2];

    const int token = blockIdx.x;
    const int tid = threadIdx.x;
    const int w = tid >> 5, lane = tid & 31;
    const float* kvp = cfc + (size_t)token * (M_DIM * L_DIM);

    // ================= Q side =================
    {
        float qs = 0.f, qs2 = 0.f;
        #pragma unroll
        for (int i = 0; i < 4; i++) {
            int d = tid + i * 256;
            float v = base[(size_t)token * D_DIM + d];
            s_xq[d] = v; qs += v; qs2 += v * v;
        }
        #pragma unroll
        for (int o = 16; o > 0; o >>= 1) {
            qs  += __shfl_xor_sync(0xffffffffu, qs, o);
            qs2 += __shfl_xor_sync(0xffffffffu, qs2, o);
        }
        if (lane == 0) { s_red[w][0] = qs; s_red[w][1] = qs2; }
        #pragma unroll
        for (int i = 0; i < 4; i++) { int d = tid + i * 256; s_xq[d] *= qg[d]; }
        __syncthreads();
        if (tid == 0) {
            float S = 0.f, S2 = 0.f;
            #pragma unroll
            for (int i = 0; i < 8; i++) { S += s_red[i][0]; S2 += s_red[i][1]; }
            float mu = S * (1.f / D_DIM);
            float var = S2 * (1.f / D_DIM) - mu * mu;
            s_qstat[0] = mu; s_qstat[1] = rsqrtf(var + LN_EPS);
        }
        __syncthreads();
        float qmu = s_qstat[0], qr = s_qstat[1];
        #pragma unroll
        for (int jj = 0; jj < 4; jj++) {
            int j = w * 4 + jj;
            const float* wq = Wq + j * D_DIM;
            float p = 0.f;
            for (int d = lane; d < D_DIM; d += 32) p += wq[d] * s_xq[d];
            #pragma unroll
            for (int o = 16; o > 0; o >>= 1) p += __shfl_xor_sync(0xffffffffu, p, o);
            if (lane == 0) s_qlow[j] = qr * (p - qmu * g_Sq[j]) + g_Cq[j];
        }
    }

    // ================= K pass 1: stats + projection (f32x2) =================
    ull pS[12], pQ[12], pA[12];
    #pragma unroll
    for (int i = 0; i < 12; i++) { pS[i] = 0ull; pQ[i] = 0ull; pA[i] = 0ull; }

    float4 v0, v1, v2, v3, v4, v5;
    {
        const float4* src = (const float4*)(kvp + (size_t)tid * L_DIM);
        v0 = src[0]; v1 = src[1]; v2 = src[2]; v3 = src[3]; v4 = src[4]; v5 = src[5];
    }
    for (int c = 0; c < 16; c++) {
        // stats from registers + store tile
        {
            F4U U;
            float4* dst = (float4*)(s_tile + tid * 28);
            U.f = v0; dst[0] = v0; add2(pS[0],  U.u[0]); fma2(pQ[0],  U.u[0], U.u[0]);
                                   add2(pS[1],  U.u[1]); fma2(pQ[1],  U.u[1], U.u[1]);
            U.f = v1; dst[1] = v1; add2(pS[2],  U.u[0]); fma2(pQ[2],  U.u[0], U.u[0]);
                                   add2(pS[3],  U.u[1]); fma2(pQ[3],  U.u[1], U.u[1]);
            U.f = v2; dst[2] = v2; add2(pS[4],  U.u[0]); fma2(pQ[4],  U.u[0], U.u[0]);
                                   add2(pS[5],  U.u[1]); fma2(pQ[5],  U.u[1], U.u[1]);
            U.f = v3; dst[3] = v3; add2(pS[6],  U.u[0]); fma2(pQ[6],  U.u[0], U.u[0]);
                                   add2(pS[7],  U.u[1]); fma2(pQ[7],  U.u[1], U.u[1]);
            U.f = v4; dst[4] = v4; add2(pS[8],  U.u[0]); fma2(pQ[8],  U.u[0], U.u[0]);
                                   add2(pS[9],  U.u[1]); fma2(pQ[9],  U.u[1], U.u[1]);
            U.f = v5; dst[5] = v5; add2(pS[10], U.u[0]); fma2(pQ[10], U.u[0], U.u[0]);
                                   add2(pS[11], U.u[1]); fma2(pQ[11], U.u[1], U.u[1]);
        }
        __syncthreads();
        if (c < 15) {  // prefetch next chunk, overlapped with proj FFMAs
            const float4* src = (const float4*)(kvp + (size_t)((c + 1) * 256 + tid) * L_DIM);
            v0 = src[0]; v1 = src[1]; v2 = src[2]; v3 = src[3]; v4 = src[4]; v5 = src[5];
        }
        const float* wrow = g_WgT + ((c * 256 + w * 32) * NJ) + lane;
        #pragma unroll 4
        for (int mm = 0; mm < 32; mm++) {
            float wv = wrow[mm * NJ];
            ull w2 = pack2(wv, wv);
            const float4* kk4 = (const float4*)(s_tile + (w * 32 + mm) * 28);
            F4U K0, K1, K2, K3, K4, K5;
            K0.f = kk4[0]; K1.f = kk4[1]; K2.f = kk4[2];
            K3.f = kk4[3]; K4.f = kk4[4]; K5.f = kk4[5];
            fma2(pA[0],  K0.u[0], w2); fma2(pA[1],  K0.u[1], w2);
            fma2(pA[2],  K1.u[0], w2); fma2(pA[3],  K1.u[1], w2);
            fma2(pA[4],  K2.u[0], w2); fma2(pA[5],  K2.u[1], w2);
            fma2(pA[6],  K3.u[0], w2); fma2(pA[7],  K3.u[1], w2);
            fma2(pA[8],  K4.u[0], w2); fma2(pA[9],  K4.u[1], w2);
            fma2(pA[10], K5.u[0], w2); fma2(pA[11], K5.u[1], w2);
        }
        __syncthreads();
    }

    // unpack packed accumulators
    float ps[L_DIM], ps2[L_DIM], pacc[L_DIM];
    #pragma unroll
    for (int i = 0; i < 12; i++) {
        unpack2(pS[i], ps[2 * i],  ps[2 * i + 1]);
        unpack2(pQ[i], ps2[2 * i], ps2[2 * i + 1]);
        unpack2(pA[i], pacc[2 * i], pacc[2 * i + 1]);
    }

    // stats reduce across block
    #pragma unroll
    for (int l = 0; l < L_DIM; l++) {
        float a = ps[l], b = ps2[l];
        #pragma unroll
        for (int o = 16; o > 0; o >>= 1) {
            a += __shfl_xor_sync(0xffffffffu, a, o);
            b += __shfl_xor_sync(0xffffffffu, b, o);
        }
        if (lane == 0) { s_red[w][l] = a; s_red[w][24 + l] = b; }
    }
    __syncthreads();
    if (tid < L_DIM) {
        float S = 0.f, S2 = 0.f;
        #pragma unroll
        for (int i = 0; i < 8; i++) { S += s_red[i][tid]; S2 += s_red[i][24 + tid]; }
        float mu = S * (1.f / M_DIM);
        float var = S2 * (1.f / M_DIM) - mu * mu;
        s_mu[tid] = mu; s_rstd[tid] = rsqrtf(var + LN_EPS);
    }
    // proj reduce across warps (reuse tile smem)
    float* pr = s_tile;   // [w][l*32+j]
    #pragma unroll
    for (int l = 0; l < L_DIM; l++) pr[w * 768 + l * 32 + lane] = pacc[l];
    __syncthreads();
    for (int e = tid; e < 768; e += 256) {
        float P = 0.f;
        #pragma unroll
        for (int i = 0; i < 8; i++) P += pr[i * 768 + e];
        int l = e >> 5, j = e & 31;
        s_klow[e] = s_rstd[l] * (P - s_mu[l] * g_Swg[j]) + g_Ck[j];
    }
    __syncthreads();

    // ================= scores + softmax =================
    if (tid < H_DIM * L_DIM) {
        int h = tid / L_DIM, l = tid - h * L_DIM;
        float s = 0.f;
        #pragma unroll
        for (int d = 0; d < HD; d++) s += s_qlow[h * HD + d] * s_klow[l * NJ + h * HD + d];
        s *= SCORE_SCALE;
        if (isnan(s)) s = -INFINITY;
        s_scores[h][l] = s;
    }
    __syncthreads();
    if (tid < H_DIM) {
        int h = tid;
        float mx = -INFINITY;
        #pragma unroll
        for (int l = 0; l < L_DIM; l++) mx = fmaxf(mx, s_scores[h][l]);
        float e[L_DIM]; float sum = 0.f;
        #pragma unroll
        for (int l = 0; l < L_DIM; l++) { e[l] = expf(s_scores[h][l] - mx); sum += e[l]; }
        float inv = 1.f / sum;
        float ch = 0.f;
        #pragma unroll
        for (int l = 0; l < L_DIM; l++) {
            float wv = e[l] * inv * s_rstd[l];
            s_w[h][l] = wv;
            ch += wv * s_mu[l];
        }
        s_ch[h] = ch;
    }
    __syncthreads();

    // ================= K pass 2: out[h][m] (f32x2) =================
    const float ch0 = s_ch[0], ch1 = s_ch[1], ch2 = s_ch[2], ch3 = s_ch[3];
    float* outp = g_OUT + (size_t)token * (H_DIM * M_DIM);
    for (int c = 0; c < 16; c++) {
        int m = c * 256 + tid;
        const float4* src = (const float4*)(kvp + (size_t)m * L_DIM);
        F4U kvu[6];
        #pragma unroll
        for (int i = 0; i < 6; i++) kvu[i].f = src[i];
        ull a0 = 0ull, a1 = 0ull, a2 = 0ull, a3 = 0ull;
        #pragma unroll
        for (int l4 = 0; l4 < 6; l4++) {
            F4U W0, W1, W2, W3;
            W0.f = *(const float4*)&s_w[0][l4 * 4];
            W1.f = *(const float4*)&s_w[1][l4 * 4];
            W2.f = *(const float4*)&s_w[2][l4 * 4];
            W3.f = *(const float4*)&s_w[3][l4 * 4];
            fma2(a0, kvu[l4].u[0], W0.u[0]); fma2(a0, kvu[l4].u[1], W0.u[1]);
            fma2(a1, kvu[l4].u[0], W1.u[0]); fma2(a1, kvu[l4].u[1], W1.u[1]);
            fma2(a2, kvu[l4].u[0], W2.u[0]); fma2(a2, kvu[l4].u[1], W2.u[1]);
            fma2(a3, kvu[l4].u[0], W3.u[0]); fma2(a3, kvu[l4].u[1], W3.u[1]);
        }
        float x, y, A0, A1, A2, A3;
        unpack2(a0, x, y); A0 = x + y;
        unpack2(a1, x, y); A1 = x + y;
        unpack2(a2, x, y); A2 = x + y;
        unpack2(a3, x, y); A3 = x + y;
        float gm = kg[m], bm = kb[m];
        outp[0 * M_DIM + m] = gm * (A0 - ch0) + bm;
        outp[1 * M_DIM + m] = gm * (A1 - ch1) + bm;
        outp[2 * M_DIM + m] = gm * (A2 - ch2) + bm;
        outp[3 * M_DIM + m] = gm * (A3 - ch3) + bm;
    }
}

// ---------------------------------------------------------
// Y = OUT (2048 x 16384) @ outB^T (16384 x 64), split-K(8) with atomics, f32x2.
__global__ __launch_bounds__(128) void k_y(const float* __restrict__ outB) {
    __shared__ __align__(16) float sB[64 * 66];
    __shared__ __align__(16) float sO[64 * 20];
    const int bt = blockIdx.x & 127;      // token tile (16 tokens)
    const int ks = blockIdx.x >> 7;       // K split (0..7)
    const int tid = threadIdx.x;
    const int r2 = (tid & 31) * 2;
    const int tg = tid >> 5;              // token group (4 tokens)
    ull acc00 = 0ull, acc01 = 0ull, acc10 = 0ull, acc11 = 0ull;
    const int k0base = ks * 2048;
    const float* outp = g_OUT + (size_t)bt * 16 * 16384;

    for (int kt = 0; kt < 32; kt++) {
        int k0 = k0base + kt * 64;
        for (int i = tid; i < 4096; i += 128) {
            int r = i >> 6, kk = i & 63;
            sB[kk * 66 + r] = outB[(size_t)r * 16384 + k0 + kk];
        }
        for (int i = tid; i < 1024; i += 128) {
            int t = i >> 6, kk = i & 63;
            sO[kk * 20 + t] = outp[(size_t)t * 16384 + k0 + kk];
        }
        __syncthreads();
        #pragma unroll 8
        for (int kk = 0; kk < 64; kk++) {
            float2 b2 = *(const float2*)&sB[kk * 66 + r2];
            ull bx = pack2(b2.x, b2.x);
            ull by = pack2(b2.y, b2.y);
            F4U O; O.f = *(const float4*)&sO[kk * 20 + tg * 4];
            fma2(acc00, O.u[0], bx); fma2(acc10, O.u[0], by);
            fma2(acc01, O.u[1], bx); fma2(acc11, O.u[1], by);
        }
        __syncthreads();
    }
    int tbase = bt * 16 + tg * 4;
    float t0, t1, t2, t3;
    unpack2(acc00, t0, t1); unpack2(acc01, t2, t3);
    atomicAdd(&g_Y[(tbase + 0) * R_DIM + r2], t0);
    atomicAdd(&g_Y[(tbase + 1) * R_DIM + r2], t1);
    atomicAdd(&g_Y[(tbase + 2) * R_DIM + r2], t2);
    atomicAdd(&g_Y[(tbase + 3) * R_DIM + r2], t3);
    unpack2(acc10, t0, t1); unpack2(acc11, t2, t3);
    atomicAdd(&g_Y[(tbase + 0) * R_DIM + r2 + 1], t0);
    atomicAdd(&g_Y[(tbase + 1) * R_DIM + r2 + 1], t1);
    atomicAdd(&g_Y[(tbase + 2) * R_DIM + r2 + 1], t2);
    atomicAdd(&g_Y[(tbase + 3) * R_DIM + r2 + 1], t3);
}

// ---------------------------------------------------------
// result = base + scale * (Y @ outA^T + out_bias)
__global__ __launch_bounds__(256) void k_final(
    const float* __restrict__ base, const float* __restrict__ outA,
    const float* __restrict__ out_bias, const float* __restrict__ scale_p,
    float* __restrict__ out)
{
    __shared__ __align__(16) float yc[8][64];
    const int t0 = blockIdx.x * 8;
    const int tid = threadIdx.x;
    for (int e = tid; e < 512; e += 256) yc[e >> 6][e & 63] = g_Y[t0 * R_DIM + e];
    __syncthreads();
    const float scale = *scale_p;
    for (int d = tid; d < D_DIM; d += 256) {
        const float4* ar = (const float4*)(outA + d * R_DIM);
        float acc[8] = {0.f, 0.f, 0.f, 0.f, 0.f, 0.f, 0.f, 0.f};
        #pragma unroll
        for (int rr = 0; rr < 16; rr++) {
            float4 a = ar[rr];
            #pragma unroll
            for (int tt = 0; tt < 8; tt++) {
                float4 y4 = *(const float4*)&yc[tt][rr * 4];
                acc[tt] += a.x * y4.x + a.y * y4.y + a.z * y4.z + a.w * y4.w;
            }
        }
        float bias = out_bias[d];
        #pragma unroll
        for (int tt = 0; tt < 8; tt++) {
            int t = t0 + tt;
            out[(size_t)t * D_DIM + d] = base[(size_t)t * D_DIM + d] + scale * (acc[tt] + bias);
        }
    }
}

// ---------------------------------------------------------
extern "C" void kernel_launch(void* const* d_in, const int* in_sizes, int n_in,
                              void* d_out, int out_size) {
    const float* base  = (const float*)d_in[0];
    const float* cfc   = (const float*)d_in[1];
    const float* qg    = (const float*)d_in[2];
    const float* qb    = (const float*)d_in[3];
    const float* kg    = (const float*)d_in[4];
    const float* kb    = (const float*)d_in[5];
    const float* Wq    = (const float*)d_in[6];
    const float* bq    = (const float*)d_in[7];
    const float* Wk    = (const float*)d_in[8];
    const float* bk    = (const float*)d_in[9];
    const float* outA  = (const float*)d_in[10];
    const float* outB  = (const float*)d_in[11];
    const float* obias = (const float*)d_in[12];
    const float* ascale= (const float*)d_in[13];
    float* out = (float*)d_out;

    k_pre_wgt<<<512, 256>>>(Wk, kg);
    k_pre_sc<<<64, 256>>>(Wk, kg, kb, bk, Wq, qg, qb, bq);
    k_zero_y<<<512, 256>>>();
    k_main<<<NT, 256>>>(base, cfc, qg, kg, kb, Wq);
    k_y<<<1024, 128>>>(outB);
    k_final<<<NT / 8, 256>>>(base, outA, obias, ascale, out);
}